// round 2
// baseline (speedup 1.0000x reference)
#include <cuda_runtime.h>
#include <cuda_bf16.h>
#include <cstdint>

// ============================================================================
// NSFPRawMLP: x[262144,3] -> 128 -> (7x 128x128 + ReLU) -> 3
// Base-target tensor path: mma.sync m16n8k16 bf16 with fp32 accum.
// Precision: split-GEMM  C = Ahi*Whi + Ahi*Wlo + Alo*Whi  (error ~2^-17).
// Weights pre-split/pre-swizzled by a prep kernel; streamed L2->SMEM with
// cp.async double buffering. Activations live entirely in registers as
// mma fragments; layer N's accumulator IS layer N+1's A operand.
// ============================================================================

#define NROWS   262144
#define NHID    7
#define NTILES  (NROWS / 128)       // 2048 CTAs, 128 rows each
#define THREADS 256                 // 8 warps, 16 rows/warp

// Weight images: [layer][65536 B]: hi bf16 image at +0, lo at +32768.
// Image layout: byte = n*256 + ((chunk ^ (n&7))<<4) + (k&7)*2, chunk = k>>3.
// (XOR-swizzled 16B chunks -> conflict-free ldmatrix.)
static __device__ __align__(16) unsigned char g_wimg[NHID][65536];

// ---------------------------------------------------------------------------
// SMEM layout (dynamic)
// ---------------------------------------------------------------------------
#define SM_WBUF    0                 // 2 x 65536
#define SM_BIAS    131072            // 7*128 f32 = 3584
#define SM_W0      (SM_BIAS + 3584)  // 128*3 f32 = 1536
#define SM_B0      (SM_W0 + 1536)    // 128 f32  = 512
#define SM_WOUT    (SM_B0 + 512)     // 3*128 f32 = 1536
#define SM_BOUT    (SM_WOUT + 1536)  // 16
#define SMEM_SZ    (SM_BOUT + 16)

// ---------------------------------------------------------------------------
// PTX helpers (all base-target, sm_80+)
// ---------------------------------------------------------------------------
__device__ __forceinline__ uint32_t smem_u32(const void* p) {
    uint32_t a;
    asm("{ .reg .u64 t; cvta.to.shared.u64 t, %1; cvt.u32.u64 %0, t; }"
        : "=r"(a) : "l"(p));
    return a;
}

#define CP_ASYNC16(dst_u32, src_ptr) \
    asm volatile("cp.async.cg.shared.global [%0], [%1], 16;" \
                 :: "r"(dst_u32), "l"(src_ptr) : "memory")
#define CP_COMMIT() asm volatile("cp.async.commit_group;" ::: "memory")
#define CP_WAIT(n)  asm volatile("cp.async.wait_group %0;" :: "n"(n) : "memory")

#define LDSM4(r0, r1, r2, r3, addr) \
    asm volatile("ldmatrix.sync.aligned.m8n8.x4.shared.b16 {%0,%1,%2,%3}, [%4];" \
                 : "=r"(r0), "=r"(r1), "=r"(r2), "=r"(r3) : "r"(addr))

#define MMA16816(C, A, b0_, b1_) \
    asm volatile("mma.sync.aligned.m16n8k16.row.col.f32.bf16.bf16.f32 " \
                 "{%0,%1,%2,%3},{%4,%5,%6,%7},{%8,%9},{%0,%1,%2,%3};" \
                 : "+f"((C)[0]), "+f"((C)[1]), "+f"((C)[2]), "+f"((C)[3]) \
                 : "r"((A)[0]), "r"((A)[1]), "r"((A)[2]), "r"((A)[3]), \
                   "r"(b0_), "r"(b1_))

// truncation split: v = hi(bf16 trunc) + lo(bf16 rn); packs a pair (v0 low).
__device__ __forceinline__ void split_pair(float v0, float v1,
                                           uint32_t& hi_pk, uint32_t& lo_pk) {
    uint32_t u0 = __float_as_uint(v0), u1 = __float_as_uint(v1);
    hi_pk = __byte_perm(u0, u1, 0x7632);          // {v1.hi16 : v0.hi16}
    float l0 = v0 - __uint_as_float(u0 & 0xFFFF0000u);
    float l1 = v1 - __uint_as_float(u1 & 0xFFFF0000u);
    asm("cvt.rn.bf16x2.f32 %0, %1, %2;" : "=r"(lo_pk) : "f"(l1), "f"(l0));
}

__device__ __forceinline__ float relu(float v) { return fmaxf(v, 0.0f); }

// ---------------------------------------------------------------------------
// Prep kernel: split Wh fp32 -> (hi,lo) bf16 into the swizzled image.
// ---------------------------------------------------------------------------
__global__ void prep_weights_kernel(const float* __restrict__ Wh) {
    int idx = blockIdx.x * blockDim.x + threadIdx.x;
    if (idx >= NHID * 128 * 128) return;
    int l = idx >> 14;
    int n = (idx >> 7) & 127;     // out feature
    int k = idx & 127;            // in feature
    float v = Wh[idx];
    uint32_t u = __float_as_uint(v);
    unsigned short hi = (unsigned short)(u >> 16);
    float lof = v - __uint_as_float(u & 0xFFFF0000u);
    __nv_bfloat16 lo = __float2bfloat16(lof);
    uint32_t chunk = (uint32_t)k >> 3;
    uint32_t off = (uint32_t)n * 256 + ((chunk ^ ((uint32_t)n & 7)) << 4)
                 + ((uint32_t)k & 7) * 2;
    *(unsigned short*)&g_wimg[l][off]         = hi;
    *(unsigned short*)&g_wimg[l][off + 32768] = *(unsigned short*)&lo;
}

// ---------------------------------------------------------------------------
// Main kernel
// ---------------------------------------------------------------------------
__global__ void __launch_bounds__(THREADS, 1)
mlp_kernel(const float* __restrict__ x,
           const float* __restrict__ W0,
           const float* __restrict__ b0,
           const float* __restrict__ bh,
           const float* __restrict__ Wout,
           const float* __restrict__ bout,
           float* __restrict__ out) {
    extern __shared__ char smem[];
    const uint32_t sb = smem_u32(smem);
    const int tid  = threadIdx.x;
    const int wid  = tid >> 5;
    const int lane = tid & 31;
    const int q    = lane & 3;          // quad index (col pair selector)

    // ---- kick off layer-0 weight prefetch immediately ----
    {
        const char* src = (const char*)&g_wimg[0][0];
        uint32_t dst = sb + SM_WBUF;
        #pragma unroll
        for (int i = 0; i < 16; i++)
            CP_ASYNC16(dst + (uint32_t)(tid + i * 256) * 16,
                       src + (size_t)(tid + i * 256) * 16);
        CP_COMMIT();
    }

    // ---- stage small params ----
    {
        float* bias_s = (float*)(smem + SM_BIAS);
        for (int i = tid; i < NHID * 128; i += THREADS) bias_s[i] = bh[i];
        float* w0s = (float*)(smem + SM_W0);
        if (tid < 128) {
            w0s[tid * 3 + 0] = W0[tid * 3 + 0];
            w0s[tid * 3 + 1] = W0[tid * 3 + 1];
            w0s[tid * 3 + 2] = W0[tid * 3 + 2];
            ((float*)(smem + SM_B0))[tid] = b0[tid];
        }
        float* wos = (float*)(smem + SM_WOUT);
        for (int i = tid; i < 384; i += THREADS) wos[i] = Wout[i];
        if (tid < 3) ((float*)(smem + SM_BOUT))[tid] = bout[tid];
    }
    __syncthreads();

    // global rows owned by this thread (2 per thread, m16 tile per warp)
    const int rbase = blockIdx.x * 128 + wid * 16 + (lane >> 2);
    const int g0 = rbase;        // rows t/4
    const int g1 = rbase + 8;    // rows t/4 + 8

    // ---- layer 0: [3 -> 128] in fp32 FFMA, produce A fragments ----
    uint32_t Ahi[8][4], Alo[8][4];
    {
        const float x00 = x[g0 * 3 + 0], x01 = x[g0 * 3 + 1], x02 = x[g0 * 3 + 2];
        const float x10 = x[g1 * 3 + 0], x11 = x[g1 * 3 + 1], x12 = x[g1 * 3 + 2];
        const float* w0s = (const float*)(smem + SM_W0);
        const float* b0s = (const float*)(smem + SM_B0);
        #pragma unroll
        for (int s = 0; s < 8; s++) {
            const int c0 = 16 * s + 2 * q;       // cols c0, c0+1
            const int c2 = c0 + 8;               // cols c2, c2+1
            #pragma unroll
            for (int h = 0; h < 2; h++) {        // h=0 -> c0 pair, h=1 -> c2 pair
                const int ca = h ? c2 : c0;
                const float wa0 = w0s[ca * 3 + 0], wa1 = w0s[ca * 3 + 1], wa2 = w0s[ca * 3 + 2];
                const float wb0 = w0s[(ca + 1) * 3 + 0], wb1 = w0s[(ca + 1) * 3 + 1], wb2 = w0s[(ca + 1) * 3 + 2];
                const float ba = b0s[ca], bb = b0s[ca + 1];
                float v00 = relu(fmaf(x00, wa0, fmaf(x01, wa1, fmaf(x02, wa2, ba))));
                float v01 = relu(fmaf(x00, wb0, fmaf(x01, wb1, fmaf(x02, wb2, bb))));
                float v10 = relu(fmaf(x10, wa0, fmaf(x11, wa1, fmaf(x12, wa2, ba))));
                float v11 = relu(fmaf(x10, wb0, fmaf(x11, wb1, fmaf(x12, wb2, bb))));
                split_pair(v00, v01, Ahi[s][2 * h + 0], Alo[s][2 * h + 0]);
                split_pair(v10, v11, Ahi[s][2 * h + 1], Alo[s][2 * h + 1]);
            }
        }
    }

    // per-thread ldmatrix address pieces
    const uint32_t nloc = (uint32_t)((lane & 7) + ((lane >> 4) & 1) * 8); // 0..15
    const uint32_t jbit = (uint32_t)((lane >> 3) & 1);                   // chunk +1
    uint32_t swz[8];
    #pragma unroll
    for (int s = 0; s < 8; s++)
        swz[s] = nloc * 256 + ((((uint32_t)(2 * s) + jbit) ^ (nloc & 7)) << 4);

    const float* bias_s = (const float*)(smem + SM_BIAS);
    const float* wout_s = (const float*)(smem + SM_WOUT);
    const float* bout_s = (const float*)(smem + SM_BOUT);

    // ---- 7 hidden layers ----
    #pragma unroll 1
    for (int l = 0; l < NHID; l++) {
        __syncthreads();   // everyone done reading buf[(l-1)&1]
        if (l + 1 < NHID) {
            const char* src = (const char*)&g_wimg[l + 1][0];
            uint32_t dst = sb + SM_WBUF + (uint32_t)((l + 1) & 1) * 65536;
            #pragma unroll
            for (int i = 0; i < 16; i++)
                CP_ASYNC16(dst + (uint32_t)(tid + i * 256) * 16,
                           src + (size_t)(tid + i * 256) * 16);
            CP_COMMIT();
            CP_WAIT(1);            // buf[l&1] complete
        } else {
            CP_WAIT(0);
        }
        __syncthreads();

        const uint32_t wb = sb + SM_WBUF + (uint32_t)(l & 1) * 65536;

        float C[16][4];
        #pragma unroll
        for (int g = 0; g < 16; g++)
            { C[g][0] = 0.f; C[g][1] = 0.f; C[g][2] = 0.f; C[g][3] = 0.f; }

        #pragma unroll
        for (int s = 0; s < 8; s++) {
            #pragma unroll
            for (int p = 0; p < 8; p++) {
                const uint32_t ah = wb + (uint32_t)p * 4096 + swz[s];
                uint32_t h0, h1, h2, h3, l0, l1, l2, l3;
                LDSM4(h0, h1, h2, h3, ah);           // Whi frags, groups 2p, 2p+1
                MMA16816(C[2 * p],     Ahi[s], h0, h1);
                MMA16816(C[2 * p + 1], Ahi[s], h2, h3);
                MMA16816(C[2 * p],     Alo[s], h0, h1);
                MMA16816(C[2 * p + 1], Alo[s], h2, h3);
                LDSM4(l0, l1, l2, l3, ah + 32768);   // Wlo frags
                MMA16816(C[2 * p],     Ahi[s], l0, l1);
                MMA16816(C[2 * p + 1], Ahi[s], l2, l3);
            }
        }

        const float* bl = bias_s + l * 128;

        if (l < NHID - 1) {
            // bias + relu + split -> next layer A fragments
            #pragma unroll
            for (int s = 0; s < 8; s++) {
                const float2 bb0 = *(const float2*)&bl[16 * s + 2 * q];
                const float2 bb1 = *(const float2*)&bl[16 * s + 8 + 2 * q];
                float v00 = relu(C[2 * s][0] + bb0.x);
                float v01 = relu(C[2 * s][1] + bb0.y);
                float v10 = relu(C[2 * s][2] + bb0.x);
                float v11 = relu(C[2 * s][3] + bb0.y);
                split_pair(v00, v01, Ahi[s][0], Alo[s][0]);
                split_pair(v10, v11, Ahi[s][1], Alo[s][1]);
                float w00 = relu(C[2 * s + 1][0] + bb1.x);
                float w01 = relu(C[2 * s + 1][1] + bb1.y);
                float w10 = relu(C[2 * s + 1][2] + bb1.x);
                float w11 = relu(C[2 * s + 1][3] + bb1.y);
                split_pair(w00, w01, Ahi[s][2], Alo[s][2]);
                split_pair(w10, w11, Ahi[s][3], Alo[s][3]);
            }
        } else {
            // final: bias + relu, fused [128 -> 3] projection + bout
            float o00 = 0.f, o01 = 0.f, o02 = 0.f;   // row g0
            float o10 = 0.f, o11 = 0.f, o12 = 0.f;   // row g1
            #pragma unroll
            for (int g = 0; g < 16; g++) {
                const int c = 8 * g + 2 * q;
                const float2 bb = *(const float2*)&bl[c];
                float v00 = relu(C[g][0] + bb.x);
                float v01 = relu(C[g][1] + bb.y);
                float v10 = relu(C[g][2] + bb.x);
                float v11 = relu(C[g][3] + bb.y);
                const float2 wj0 = *(const float2*)&wout_s[0 * 128 + c];
                const float2 wj1 = *(const float2*)&wout_s[1 * 128 + c];
                const float2 wj2 = *(const float2*)&wout_s[2 * 128 + c];
                o00 = fmaf(v00, wj0.x, fmaf(v01, wj0.y, o00));
                o01 = fmaf(v00, wj1.x, fmaf(v01, wj1.y, o01));
                o02 = fmaf(v00, wj2.x, fmaf(v01, wj2.y, o02));
                o10 = fmaf(v10, wj0.x, fmaf(v11, wj0.y, o10));
                o11 = fmaf(v10, wj1.x, fmaf(v11, wj1.y, o11));
                o12 = fmaf(v10, wj2.x, fmaf(v11, wj2.y, o12));
            }
            // reduce across the quad (lanes sharing a row)
            #pragma unroll
            for (int d = 1; d <= 2; d <<= 1) {
                o00 += __shfl_xor_sync(0xFFFFFFFF, o00, d);
                o01 += __shfl_xor_sync(0xFFFFFFFF, o01, d);
                o02 += __shfl_xor_sync(0xFFFFFFFF, o02, d);
                o10 += __shfl_xor_sync(0xFFFFFFFF, o10, d);
                o11 += __shfl_xor_sync(0xFFFFFFFF, o11, d);
                o12 += __shfl_xor_sync(0xFFFFFFFF, o12, d);
            }
            if (q == 0) {
                out[g0 * 3 + 0] = o00 + bout_s[0];
                out[g0 * 3 + 1] = o01 + bout_s[1];
                out[g0 * 3 + 2] = o02 + bout_s[2];
                out[g1 * 3 + 0] = o10 + bout_s[0];
                out[g1 * 3 + 1] = o11 + bout_s[1];
                out[g1 * 3 + 2] = o12 + bout_s[2];
            }
        }
    }
}

// ---------------------------------------------------------------------------
// kernel_launch
// ---------------------------------------------------------------------------
extern "C" void kernel_launch(void* const* d_in, const int* in_sizes, int n_in,
                              void* d_out, int out_size) {
    const float* x    = (const float*)d_in[0];   // [262144,3]
    const float* W0   = (const float*)d_in[1];   // [128,3]
    const float* b0   = (const float*)d_in[2];   // [128]
    const float* Wh   = (const float*)d_in[3];   // [7,128,128]
    const float* bh   = (const float*)d_in[4];   // [7,128]
    const float* Wout = (const float*)d_in[5];   // [3,128]
    const float* bout = (const float*)d_in[6];   // [3]
    float* out = (float*)d_out;                  // [262144,3]

    static bool attr_set = false;
    if (!attr_set) {
        cudaFuncSetAttribute(mlp_kernel,
                             cudaFuncAttributeMaxDynamicSharedMemorySize, SMEM_SZ);
        attr_set = true;
    }

    prep_weights_kernel<<<(NHID * 128 * 128 + 255) / 256, 256>>>(Wh);
    mlp_kernel<<<NTILES, THREADS, SMEM_SZ>>>(x, W0, b0, bh, Wout, bout, out);
}